// round 1
// baseline (speedup 1.0000x reference)
#include <cuda_runtime.h>
#include <math.h>
#include <stdint.h>

// ---------------- problem constants ----------------
#define NB   4      // batch
#define STOT 20     // BPTT + PRED
#define BPTT 16
#define PRED 4
#define NE_  512
#define E_   256
#define NH_  8
#define HEAD_ 32
#define HID_ 512
#define NL   4
#define NVOX 512            // 8*8*8
#define NITEMS (NB*STOT)    // 80
#define NTAIL  (NB*PRED)    // 16
#define SCORE_ELEMS (NB*NE_*PRED*NVOX)   // 4194304

// ---------------- scratch (static device globals; no allocation) ----------------
__device__ float g_X  [NITEMS*NVOX*E_];
__device__ float g_H  [NITEMS*NVOX*E_];
__device__ float g_Q  [NITEMS*NVOX*E_];
__device__ float g_K  [NITEMS*NVOX*E_];
__device__ float g_V  [NITEMS*NVOX*E_];
__device__ float g_A  [NITEMS*NVOX*E_];
__device__ float g_HID[NITEMS*NVOX*HID_];
__device__ float g_XF [NTAIL*NVOX*E_];
__device__ float g_Y2 [NTAIL*NVOX*E_];
__device__ float g_Y3 [NTAIL*NVOX*E_];
__device__ float g_LG [NTAIL*NVOX*NE_];
__device__ float g_LP [NB*PRED*NVOX];

// ---------------- f32x2 helpers (Blackwell packed fp32 FMA) ----------------
__device__ __forceinline__ unsigned long long pk2(float x, float y) {
    unsigned long long r;
    asm("mov.b64 %0, {%1, %2};" : "=l"(r) : "r"(__float_as_uint(x)), "r"(__float_as_uint(y)));
    return r;
}
__device__ __forceinline__ float2 upk2(unsigned long long v) {
    unsigned int lo, hi;
    asm("mov.b64 {%0, %1}, %2;" : "=r"(lo), "=r"(hi) : "l"(v));
    return make_float2(__uint_as_float(lo), __uint_as_float(hi));
}
__device__ __forceinline__ unsigned long long fma2(unsigned long long a, unsigned long long b,
                                                   unsigned long long c) {
    unsigned long long d;
    asm("fma.rn.f32x2 %0, %1, %2, %3;" : "=l"(d) : "l"(a), "l"(b), "l"(c));
    return d;
}

__device__ __forceinline__ float gelu_exact(float x) {
    return 0.5f * x * (1.0f + erff(x * 0.70710678118654752f));
}

// ---------------- embedding ----------------
__global__ void embed_kernel(const int* __restrict__ code, const float* __restrict__ emb,
                             const float* __restrict__ pos, float* __restrict__ X) {
    long idx = (long)blockIdx.x * 256 + threadIdx.x;   // [0, 80*512*256)
    int c  = (int)(idx & 255);
    int p  = (int)((idx >> 8) & 511);
    int ns = (int)(idx >> 17);          // b*20 + s
    int s  = ns % STOT;
    int b  = ns / STOT;
    int tok = (s < BPTT) ? code[(b * BPTT + s) * NVOX + p] : NE_;
    X[idx] = emb[tok * E_ + c] + pos[s * E_ + c];
}

// ---------------- layernorm (warp per row of 256) ----------------
__global__ void ln_kernel(const float* __restrict__ in, float* __restrict__ out,
                          const float* __restrict__ gam, const float* __restrict__ bet,
                          int rows, int s_count, int S_total, int s_off) {
    int w    = (int)((blockIdx.x * (long)blockDim.x + threadIdx.x) >> 5);
    int lane = threadIdx.x & 31;
    if (w >= rows) return;
    int n = w >> 9, p = w & 511;
    int bb = n / s_count, ss = s_off + n % s_count;
    const float* src = in + ((long)(bb * S_total + ss) * NVOX + p) * E_;
    float4 v0 = *(const float4*)&src[lane * 4];
    float4 v1 = *(const float4*)&src[128 + lane * 4];
    float s1 = v0.x + v0.y + v0.z + v0.w + v1.x + v1.y + v1.z + v1.w;
#pragma unroll
    for (int o = 16; o; o >>= 1) s1 += __shfl_xor_sync(0xffffffffu, s1, o);
    float m = s1 * (1.0f / 256.0f);
    float d0 = v0.x - m, d1 = v0.y - m, d2 = v0.z - m, d3 = v0.w - m;
    float d4 = v1.x - m, d5 = v1.y - m, d6 = v1.z - m, d7 = v1.w - m;
    float s2 = d0*d0 + d1*d1 + d2*d2 + d3*d3 + d4*d4 + d5*d5 + d6*d6 + d7*d7;
#pragma unroll
    for (int o = 16; o; o >>= 1) s2 += __shfl_xor_sync(0xffffffffu, s2, o);
    float r = rsqrtf(s2 * (1.0f / 256.0f) + 1e-5f);
    float4 g0 = *(const float4*)&gam[lane * 4];
    float4 g1 = *(const float4*)&gam[128 + lane * 4];
    float4 b0 = *(const float4*)&bet[lane * 4];
    float4 b1 = *(const float4*)&bet[128 + lane * 4];
    float* dst = out + (long)w * E_;
    float4 o0 = make_float4(d0*r*g0.x + b0.x, d1*r*g0.y + b0.y, d2*r*g0.z + b0.z, d3*r*g0.w + b0.w);
    float4 o1 = make_float4(d4*r*g1.x + b1.x, d5*r*g1.y + b1.y, d6*r*g1.z + b1.z, d7*r*g1.w + b1.w);
    *(float4*)&dst[lane * 4] = o0;
    *(float4*)&dst[128 + lane * 4] = o1;
}

// ---------------- conv3d as implicit GEMM (fp32, packed FFMA2) ----------------
// Y[n, vox, co] = bias[co] + sum_{off, ci} X[n, nb(vox,off), ci] * W[off, ci, co]
// Tile: 128 voxels x 128 cout, BK=32, 256 threads, 8x8 microtile.
template<int CIN, int COUT, int NOFF>
__global__ __launch_bounds__(256, 2)
void conv_kernel(const float* __restrict__ Xin, const float* __restrict__ W,
                 const float* __restrict__ bias, const float* __restrict__ Res,
                 float* __restrict__ Y, int s_count, int S_total, int s_off, int doGelu) {
    __shared__ float As[32][132];   // [k][voxel], padded stride (528B, 16B-aligned)
    __shared__ float Bs[32][128];   // [k][co]
    const int n   = blockIdx.x;
    const int bb  = n / s_count, ss = s_off + n % s_count;
    const long in_base  = (long)(bb * S_total + ss) * NVOX * CIN;
    const long out_base = (long)n * NVOX * COUT;
    const int m0  = blockIdx.y * 128;
    const int co0 = blockIdx.z * 128;
    const int tid = threadIdx.x;
    const int ty = tid >> 4, tx = tid & 15;
    const int av = tid >> 3;          // A-load row base (0..31)
    const int ak = (tid & 7) * 4;     // A-load k offset
    const int bk0 = tid >> 5;         // B-load k base (0..7)
    const int bc  = (tid & 31) * 4;   // B-load co offset

    unsigned long long acc[8][4];
#pragma unroll
    for (int i = 0; i < 8; i++)
#pragma unroll
        for (int j = 0; j < 4; j++) acc[i][j] = 0ull;  // bit pattern of (0.f,0.f)

    for (int o = 0; o < NOFF; ++o) {
        int da, db, dc;
        if (NOFF == 1) { da = 0; db = 0; dc = 0; }
        else { da = o / 9 - 1; db = (o / 3) % 3 - 1; dc = o % 3 - 1; }
        for (int kc = 0; kc < CIN; kc += 32) {
#pragma unroll
            for (int it = 0; it < 4; ++it) {
                int v = it * 32 + av;
                int vox = m0 + v;
                int j0 = (vox >> 6) + da, j1 = ((vox >> 3) & 7) + db, j2 = (vox & 7) + dc;
                float4 val = make_float4(0.f, 0.f, 0.f, 0.f);
                if (((unsigned)j0 < 8u) && ((unsigned)j1 < 8u) && ((unsigned)j2 < 8u))
                    val = *(const float4*)&Xin[in_base + (long)((j0 << 6) + (j1 << 3) + j2) * CIN + kc + ak];
                As[ak + 0][v] = val.x; As[ak + 1][v] = val.y;
                As[ak + 2][v] = val.z; As[ak + 3][v] = val.w;
            }
            const float* Wo = W + ((long)o * CIN + kc) * COUT + co0;
#pragma unroll
            for (int it = 0; it < 4; ++it) {
                int k = it * 8 + bk0;
                *(float4*)&Bs[k][bc] = *(const float4*)&Wo[(long)k * COUT + bc];
            }
            __syncthreads();
#pragma unroll
            for (int kk = 0; kk < 32; ++kk) {
                float4 a0 = *(const float4*)&As[kk][ty * 4];
                float4 a1 = *(const float4*)&As[kk][64 + ty * 4];
                float4 b0 = *(const float4*)&Bs[kk][tx * 4];
                float4 b1 = *(const float4*)&Bs[kk][64 + tx * 4];
                unsigned long long bp0 = pk2(b0.x, b0.y), bp1 = pk2(b0.z, b0.w);
                unsigned long long bp2 = pk2(b1.x, b1.y), bp3 = pk2(b1.z, b1.w);
                float am[8] = {a0.x, a0.y, a0.z, a0.w, a1.x, a1.y, a1.z, a1.w};
#pragma unroll
                for (int i = 0; i < 8; i++) {
                    unsigned long long ap = pk2(am[i], am[i]);
                    acc[i][0] = fma2(ap, bp0, acc[i][0]);
                    acc[i][1] = fma2(ap, bp1, acc[i][1]);
                    acc[i][2] = fma2(ap, bp2, acc[i][2]);
                    acc[i][3] = fma2(ap, bp3, acc[i][3]);
                }
            }
            __syncthreads();
        }
    }

    float4 bias0 = *(const float4*)&bias[co0 + tx * 4];
    float4 bias1 = *(const float4*)&bias[co0 + 64 + tx * 4];
#pragma unroll
    for (int i = 0; i < 8; i++) {
        int r = (i < 4) ? (ty * 4 + i) : (64 + ty * 4 + i - 4);
        long base = out_base + (long)(m0 + r) * COUT + co0;
        float2 p0 = upk2(acc[i][0]), p1 = upk2(acc[i][1]);
        float2 p2 = upk2(acc[i][2]), p3 = upk2(acc[i][3]);
        float4 o0 = make_float4(p0.x + bias0.x, p0.y + bias0.y, p1.x + bias0.z, p1.y + bias0.w);
        float4 o1 = make_float4(p2.x + bias1.x, p2.y + bias1.y, p3.x + bias1.z, p3.y + bias1.w);
        if (Res) {
            float4 r0 = *(const float4*)&Res[base + tx * 4];
            float4 r1 = *(const float4*)&Res[base + 64 + tx * 4];
            o0.x += r0.x; o0.y += r0.y; o0.z += r0.z; o0.w += r0.w;
            o1.x += r1.x; o1.y += r1.y; o1.z += r1.z; o1.w += r1.w;
        }
        if (doGelu) {
            o0.x = gelu_exact(o0.x); o0.y = gelu_exact(o0.y);
            o0.z = gelu_exact(o0.z); o0.w = gelu_exact(o0.w);
            o1.x = gelu_exact(o1.x); o1.y = gelu_exact(o1.y);
            o1.z = gelu_exact(o1.z); o1.w = gelu_exact(o1.w);
        }
        *(float4*)&Y[base + tx * 4] = o0;
        *(float4*)&Y[base + 64 + tx * 4] = o1;
    }
}

// ---------------- attention: warp per (b, voxel, head), time length 20 ----------------
__global__ void attn_kernel(const float* __restrict__ Q, const float* __restrict__ K,
                            const float* __restrict__ V, float* __restrict__ O) {
    __shared__ float sm[4][3][STOT][33];
    __shared__ float sat[4][STOT][21];
    int w = threadIdx.x >> 5, lane = threadIdx.x & 31;
    int unit = blockIdx.x * 4 + w;          // b*4096 + p*8 + h
    int h = unit & 7, p = (unit >> 3) & 511, b = unit >> 12;
    long base0 = ((long)(b * STOT) * NVOX + p) * E_ + h * HEAD_ + lane;
    float (*q)[33] = sm[w][0];
    float (*k)[33] = sm[w][1];
    float (*v)[33] = sm[w][2];
#pragma unroll
    for (int s = 0; s < STOT; s++) {
        long idx = base0 + (long)s * NVOX * E_;
        q[s][lane] = Q[idx]; k[s][lane] = K[idx]; v[s][lane] = V[idx];
    }
    __syncwarp();
    for (int pid = lane; pid < STOT * STOT; pid += 32) {
        int s = pid / STOT, t = pid % STOT;
        float d = 0.f;
#pragma unroll
        for (int dd = 0; dd < HEAD_; dd++) d += q[s][dd] * k[t][dd];
        sat[w][s][t] = d * 0.17677669529663689f;   // 1/sqrt(32)
    }
    __syncwarp();
    for (int s = 0; s < STOT; s++) {
        float x = (lane < STOT) ? sat[w][s][lane] : -1e30f;
        float m = x;
#pragma unroll
        for (int o2 = 16; o2; o2 >>= 1) m = fmaxf(m, __shfl_xor_sync(0xffffffffu, m, o2));
        float e = (lane < STOT) ? expf(x - m) : 0.f;
        float su = e;
#pragma unroll
        for (int o2 = 16; o2; o2 >>= 1) su += __shfl_xor_sync(0xffffffffu, su, o2);
        if (lane < STOT) sat[w][s][lane] = e / su;
    }
    __syncwarp();
    for (int s = 0; s < STOT; s++) {
        float a = 0.f;
#pragma unroll
        for (int t = 0; t < STOT; t++) a += sat[w][s][t] * v[t][lane];
        O[base0 + (long)s * NVOX * E_] = a;
    }
}

// ---------------- score / loss / argmax (warp per position) ----------------
__global__ void score_kernel(const float* __restrict__ LG, const int* __restrict__ ncode,
                             float* __restrict__ out) {
    int w    = (int)((blockIdx.x * (long)blockDim.x + threadIdx.x) >> 5);
    int lane = threadIdx.x & 31;
    if (w >= NB * PRED * NVOX) return;
    const float* row = LG + (long)w * NE_;
    float vals[16];
    float bv = -1e30f; int bi = 0x7fffffff;
#pragma unroll
    for (int i = 0; i < 16; i++) {
        vals[i] = row[lane + 32 * i];
        if (vals[i] > bv) { bv = vals[i]; bi = lane + 32 * i; }
    }
#pragma unroll
    for (int o = 16; o; o >>= 1) {
        float ov = __shfl_xor_sync(0xffffffffu, bv, o);
        int   oi = __shfl_xor_sync(0xffffffffu, bi, o);
        if (ov > bv || (ov == bv && oi < bi)) { bv = ov; bi = oi; }
    }
    float m = bv;
    float se = 0.f;
#pragma unroll
    for (int i = 0; i < 16; i++) se += expf(vals[i] - m);
#pragma unroll
    for (int o = 16; o; o >>= 1) se += __shfl_xor_sync(0xffffffffu, se, o);
    float logZ = m + logf(se);
    int b = w >> 11, t = (w >> 9) & 3, p = w & 511;
#pragma unroll
    for (int i = 0; i < 16; i++) {
        int c = lane + 32 * i;
        out[(long)(((b * NE_ + c) * PRED + t) * NVOX + p)] = vals[i];
    }
    if (lane == 0) {
        int tgt = ncode[w];
        g_LP[w] = row[tgt] - logZ;
        out[SCORE_ELEMS + 1 + w] = (float)bi;
    }
}

__global__ void finish_kernel(float* __restrict__ out) {
    __shared__ float sh[256];
    float s = 0.f;
    for (int i = threadIdx.x; i < NB * PRED * NVOX; i += 256) s += g_LP[i];
    sh[threadIdx.x] = s;
    __syncthreads();
    for (int o = 128; o; o >>= 1) {
        if (threadIdx.x < o) sh[threadIdx.x] += sh[threadIdx.x + o];
        __syncthreads();
    }
    if (threadIdx.x == 0) out[SCORE_ELEMS] = -sh[0] / (float)(NB * PRED * NVOX);
}

// ---------------- driver ----------------
extern "C" void kernel_launch(void* const* d_in, const int* in_sizes, int n_in,
                              void* d_out, int out_size) {
    const int*   code  = (const int*)d_in[0];
    const int*   ncode = (const int*)d_in[1];
    const float* emb   = (const float*)d_in[2];
    const float* pos   = (const float*)d_in[3];
    const float* ln1s  = (const float*)d_in[4];
    const float* ln1b  = (const float*)d_in[5];
    const float* ln2s  = (const float*)d_in[6];
    const float* ln2b  = (const float*)d_in[7];
    const float* wq = (const float*)d_in[8];  const float* bq = (const float*)d_in[9];
    const float* wk = (const float*)d_in[10]; const float* bk = (const float*)d_in[11];
    const float* wv = (const float*)d_in[12]; const float* bv = (const float*)d_in[13];
    const float* wo = (const float*)d_in[14]; const float* bo = (const float*)d_in[15];
    const float* w1 = (const float*)d_in[16]; const float* b1 = (const float*)d_in[17];
    const float* w2 = (const float*)d_in[18]; const float* b2 = (const float*)d_in[19];
    const float* lnfs = (const float*)d_in[20]; const float* lnfb = (const float*)d_in[21];
    const float* decw = (const float*)d_in[22]; const float* decb = (const float*)d_in[23];
    const float* declns = (const float*)d_in[24]; const float* declnb = (const float*)d_in[25];
    const float* linw = (const float*)d_in[26]; const float* linb = (const float*)d_in[27];
    float* out = (float*)d_out;

    float *X, *H, *Qb, *Kb, *Vb, *Ab, *HIDb, *XFb, *Y2b, *Y3b, *LGb;
    cudaGetSymbolAddress((void**)&X,   g_X);
    cudaGetSymbolAddress((void**)&H,   g_H);
    cudaGetSymbolAddress((void**)&Qb,  g_Q);
    cudaGetSymbolAddress((void**)&Kb,  g_K);
    cudaGetSymbolAddress((void**)&Vb,  g_V);
    cudaGetSymbolAddress((void**)&Ab,  g_A);
    cudaGetSymbolAddress((void**)&HIDb,g_HID);
    cudaGetSymbolAddress((void**)&XFb, g_XF);
    cudaGetSymbolAddress((void**)&Y2b, g_Y2);
    cudaGetSymbolAddress((void**)&Y3b, g_Y3);
    cudaGetSymbolAddress((void**)&LGb, g_LG);

    embed_kernel<<<40960, 256>>>(code, emb, pos, X);

    for (int i = 0; i < NL; i++) {
        const float* wq_i = wq + (long)i * 27 * E_ * E_;
        const float* wk_i = wk + (long)i * 27 * E_ * E_;
        const float* wv_i = wv + (long)i * 27 * E_ * E_;
        const float* wo_i = wo + (long)i * 27 * E_ * E_;
        const float* w1_i = w1 + (long)i * 27 * E_ * HID_;
        const float* w2_i = w2 + (long)i * 27 * HID_ * E_;

        ln_kernel<<<5120, 256>>>(X, H, ln1s + i * E_, ln1b + i * E_, NITEMS * NVOX, STOT, STOT, 0);
        conv_kernel<E_, E_, 27><<<dim3(NITEMS, 4, 2), 256>>>(H, wq_i, bq + i * E_, nullptr, Qb, STOT, STOT, 0, 0);
        conv_kernel<E_, E_, 27><<<dim3(NITEMS, 4, 2), 256>>>(H, wk_i, bk + i * E_, nullptr, Kb, STOT, STOT, 0, 0);
        conv_kernel<E_, E_, 27><<<dim3(NITEMS, 4, 2), 256>>>(H, wv_i, bv + i * E_, nullptr, Vb, STOT, STOT, 0, 0);
        attn_kernel<<<4096, 128>>>(Qb, Kb, Vb, Ab);
        conv_kernel<E_, E_, 27><<<dim3(NITEMS, 4, 2), 256>>>(Ab, wo_i, bo + i * E_, X, X, STOT, STOT, 0, 0);
        ln_kernel<<<5120, 256>>>(X, H, ln2s + i * E_, ln2b + i * E_, NITEMS * NVOX, STOT, STOT, 0);
        conv_kernel<E_, HID_, 27><<<dim3(NITEMS, 4, 4), 256>>>(H, w1_i, b1 + i * HID_, nullptr, HIDb, STOT, STOT, 0, 1);
        conv_kernel<HID_, E_, 27><<<dim3(NITEMS, 4, 2), 256>>>(HIDb, w2_i, b2 + i * E_, X, X, STOT, STOT, 0, 0);
    }

    // tail: only s >= BPTT is needed for the score
    ln_kernel<<<1024, 256>>>(X, XFb, lnfs, lnfb, NTAIL * NVOX, PRED, STOT, BPTT);
    conv_kernel<E_, E_, 27><<<dim3(NTAIL, 4, 2), 256>>>(XFb, decw, decb, nullptr, Y2b, PRED, PRED, 0, 1);
    ln_kernel<<<1024, 256>>>(Y2b, Y3b, declns, declnb, NTAIL * NVOX, PRED, PRED, 0);
    conv_kernel<E_, NE_, 1><<<dim3(NTAIL, 4, 4), 256>>>(Y3b, linw, linb, nullptr, LGb, PRED, PRED, 0, 0);
    score_kernel<<<1024, 256>>>(LGb, ncode, out);
    finish_kernel<<<1, 256>>>(out);
}

// round 2
// speedup vs baseline: 1.0002x; 1.0002x over previous
#include <cuda_runtime.h>
#include <math.h>
#include <stdint.h>

// ---------------- problem constants ----------------
#define NB   4      // batch
#define STOT 20     // BPTT + PRED
#define BPTT 16
#define PRED 4
#define NE_  512
#define E_   256
#define NH_  8
#define HEAD_ 32
#define HID_ 512
#define NL   4
#define NVOX 512            // 8*8*8
#define NITEMS (NB*STOT)    // 80
#define NTAIL  (NB*PRED)    // 16
#define SCORE_ELEMS (NB*NE_*PRED*NVOX)   // 4194304

// ---------------- scratch (static device globals; no allocation) ----------------
__device__ float g_X  [NITEMS*NVOX*E_];
__device__ float g_H  [NITEMS*NVOX*E_];
__device__ float g_Q  [NITEMS*NVOX*E_];
__device__ float g_K  [NITEMS*NVOX*E_];
__device__ float g_V  [NITEMS*NVOX*E_];
__device__ float g_A  [NITEMS*NVOX*E_];
__device__ float g_HID[NITEMS*NVOX*HID_];
__device__ float g_XF [NTAIL*NVOX*E_];
__device__ float g_Y2 [NTAIL*NVOX*E_];
__device__ float g_Y3 [NTAIL*NVOX*E_];
__device__ float g_LG [NTAIL*NVOX*NE_];
__device__ float g_LP [NB*PRED*NVOX];

// ---------------- f32x2 helpers (Blackwell packed fp32 FMA) ----------------
__device__ __forceinline__ unsigned long long pk2(float x, float y) {
    unsigned long long r;
    asm("mov.b64 %0, {%1, %2};" : "=l"(r) : "r"(__float_as_uint(x)), "r"(__float_as_uint(y)));
    return r;
}
__device__ __forceinline__ float2 upk2(unsigned long long v) {
    unsigned int lo, hi;
    asm("mov.b64 {%0, %1}, %2;" : "=r"(lo), "=r"(hi) : "l"(v));
    return make_float2(__uint_as_float(lo), __uint_as_float(hi));
}
__device__ __forceinline__ unsigned long long fma2(unsigned long long a, unsigned long long b,
                                                   unsigned long long c) {
    unsigned long long d;
    asm("fma.rn.f32x2 %0, %1, %2, %3;" : "=l"(d) : "l"(a), "l"(b), "l"(c));
    return d;
}

__device__ __forceinline__ float gelu_exact(float x) {
    return 0.5f * x * (1.0f + erff(x * 0.70710678118654752f));
}

// ---------------- embedding ----------------
__global__ void embed_kernel(const int* __restrict__ code, const float* __restrict__ emb,
                             const float* __restrict__ pos, float* __restrict__ X) {
    long idx = (long)blockIdx.x * 256 + threadIdx.x;   // [0, 80*512*256)
    int c  = (int)(idx & 255);
    int p  = (int)((idx >> 8) & 511);
    int ns = (int)(idx >> 17);          // b*20 + s
    int s  = ns % STOT;
    int b  = ns / STOT;
    int tok = (s < BPTT) ? code[(b * BPTT + s) * NVOX + p] : NE_;
    X[idx] = emb[tok * E_ + c] + pos[s * E_ + c];
}

// ---------------- layernorm (warp per row of 256) ----------------
__global__ void ln_kernel(const float* __restrict__ in, float* __restrict__ out,
                          const float* __restrict__ gam, const float* __restrict__ bet,
                          int rows, int s_count, int S_total, int s_off) {
    int w    = (int)((blockIdx.x * (long)blockDim.x + threadIdx.x) >> 5);
    int lane = threadIdx.x & 31;
    if (w >= rows) return;
    int n = w >> 9, p = w & 511;
    int bb = n / s_count, ss = s_off + n % s_count;
    const float* src = in + ((long)(bb * S_total + ss) * NVOX + p) * E_;
    float4 v0 = *(const float4*)&src[lane * 4];
    float4 v1 = *(const float4*)&src[128 + lane * 4];
    float s1 = v0.x + v0.y + v0.z + v0.w + v1.x + v1.y + v1.z + v1.w;
#pragma unroll
    for (int o = 16; o; o >>= 1) s1 += __shfl_xor_sync(0xffffffffu, s1, o);
    float m = s1 * (1.0f / 256.0f);
    float d0 = v0.x - m, d1 = v0.y - m, d2 = v0.z - m, d3 = v0.w - m;
    float d4 = v1.x - m, d5 = v1.y - m, d6 = v1.z - m, d7 = v1.w - m;
    float s2 = d0*d0 + d1*d1 + d2*d2 + d3*d3 + d4*d4 + d5*d5 + d6*d6 + d7*d7;
#pragma unroll
    for (int o = 16; o; o >>= 1) s2 += __shfl_xor_sync(0xffffffffu, s2, o);
    float r = rsqrtf(s2 * (1.0f / 256.0f) + 1e-5f);
    float4 g0 = *(const float4*)&gam[lane * 4];
    float4 g1 = *(const float4*)&gam[128 + lane * 4];
    float4 b0 = *(const float4*)&bet[lane * 4];
    float4 b1 = *(const float4*)&bet[128 + lane * 4];
    float* dst = out + (long)w * E_;
    float4 o0 = make_float4(d0*r*g0.x + b0.x, d1*r*g0.y + b0.y, d2*r*g0.z + b0.z, d3*r*g0.w + b0.w);
    float4 o1 = make_float4(d4*r*g1.x + b1.x, d5*r*g1.y + b1.y, d6*r*g1.z + b1.z, d7*r*g1.w + b1.w);
    *(float4*)&dst[lane * 4] = o0;
    *(float4*)&dst[128 + lane * 4] = o1;
}

// ---------------- conv3d as implicit GEMM (fp32, packed FFMA2) ----------------
// Y[n, vox, co] = bias[co] + sum_{off, ci} X[n, nb(vox,off), ci] * W[off, ci, co]
// Tile: 128 voxels x 128 cout, BK=32, 256 threads, 8x8 microtile.
template<int CIN, int COUT, int NOFF>
__global__ __launch_bounds__(256, 2)
void conv_kernel(const float* __restrict__ Xin, const float* __restrict__ W,
                 const float* __restrict__ bias, const float* __restrict__ Res,
                 float* __restrict__ Y, int s_count, int S_total, int s_off, int doGelu) {
    __shared__ float As[32][132];   // [k][voxel], padded stride (528B, 16B-aligned)
    __shared__ float Bs[32][128];   // [k][co]
    const int n   = blockIdx.x;
    const int bb  = n / s_count, ss = s_off + n % s_count;
    const long in_base  = (long)(bb * S_total + ss) * NVOX * CIN;
    const long out_base = (long)n * NVOX * COUT;
    const int m0  = blockIdx.y * 128;
    const int co0 = blockIdx.z * 128;
    const int tid = threadIdx.x;
    const int ty = tid >> 4, tx = tid & 15;
    const int av = tid >> 3;          // A-load row base (0..31)
    const int ak = (tid & 7) * 4;     // A-load k offset
    const int bk0 = tid >> 5;         // B-load k base (0..7)
    const int bc  = (tid & 31) * 4;   // B-load co offset

    unsigned long long acc[8][4];
#pragma unroll
    for (int i = 0; i < 8; i++)
#pragma unroll
        for (int j = 0; j < 4; j++) acc[i][j] = 0ull;  // bit pattern of (0.f,0.f)

    for (int o = 0; o < NOFF; ++o) {
        int da, db, dc;
        if (NOFF == 1) { da = 0; db = 0; dc = 0; }
        else { da = o / 9 - 1; db = (o / 3) % 3 - 1; dc = o % 3 - 1; }
        for (int kc = 0; kc < CIN; kc += 32) {
#pragma unroll
            for (int it = 0; it < 4; ++it) {
                int v = it * 32 + av;
                int vox = m0 + v;
                int j0 = (vox >> 6) + da, j1 = ((vox >> 3) & 7) + db, j2 = (vox & 7) + dc;
                float4 val = make_float4(0.f, 0.f, 0.f, 0.f);
                if (((unsigned)j0 < 8u) && ((unsigned)j1 < 8u) && ((unsigned)j2 < 8u))
                    val = *(const float4*)&Xin[in_base + (long)((j0 << 6) + (j1 << 3) + j2) * CIN + kc + ak];
                As[ak + 0][v] = val.x; As[ak + 1][v] = val.y;
                As[ak + 2][v] = val.z; As[ak + 3][v] = val.w;
            }
            const float* Wo = W + ((long)o * CIN + kc) * COUT + co0;
#pragma unroll
            for (int it = 0; it < 4; ++it) {
                int k = it * 8 + bk0;
                *(float4*)&Bs[k][bc] = *(const float4*)&Wo[(long)k * COUT + bc];
            }
            __syncthreads();
#pragma unroll
            for (int kk = 0; kk < 32; ++kk) {
                float4 a0 = *(const float4*)&As[kk][ty * 4];
                float4 a1 = *(const float4*)&As[kk][64 + ty * 4];
                float4 b0 = *(const float4*)&Bs[kk][tx * 4];
                float4 b1 = *(const float4*)&Bs[kk][64 + tx * 4];
                unsigned long long bp0 = pk2(b0.x, b0.y), bp1 = pk2(b0.z, b0.w);
                unsigned long long bp2 = pk2(b1.x, b1.y), bp3 = pk2(b1.z, b1.w);
                float am[8] = {a0.x, a0.y, a0.z, a0.w, a1.x, a1.y, a1.z, a1.w};
#pragma unroll
                for (int i = 0; i < 8; i++) {
                    unsigned long long ap = pk2(am[i], am[i]);
                    acc[i][0] = fma2(ap, bp0, acc[i][0]);
                    acc[i][1] = fma2(ap, bp1, acc[i][1]);
                    acc[i][2] = fma2(ap, bp2, acc[i][2]);
                    acc[i][3] = fma2(ap, bp3, acc[i][3]);
                }
            }
            __syncthreads();
        }
    }

    float4 bias0 = *(const float4*)&bias[co0 + tx * 4];
    float4 bias1 = *(const float4*)&bias[co0 + 64 + tx * 4];
#pragma unroll
    for (int i = 0; i < 8; i++) {
        int r = (i < 4) ? (ty * 4 + i) : (64 + ty * 4 + i - 4);
        long base = out_base + (long)(m0 + r) * COUT + co0;
        float2 p0 = upk2(acc[i][0]), p1 = upk2(acc[i][1]);
        float2 p2 = upk2(acc[i][2]), p3 = upk2(acc[i][3]);
        float4 o0 = make_float4(p0.x + bias0.x, p0.y + bias0.y, p1.x + bias0.z, p1.y + bias0.w);
        float4 o1 = make_float4(p2.x + bias1.x, p2.y + bias1.y, p3.x + bias1.z, p3.y + bias1.w);
        if (Res) {
            float4 r0 = *(const float4*)&Res[base + tx * 4];
            float4 r1 = *(const float4*)&Res[base + 64 + tx * 4];
            o0.x += r0.x; o0.y += r0.y; o0.z += r0.z; o0.w += r0.w;
            o1.x += r1.x; o1.y += r1.y; o1.z += r1.z; o1.w += r1.w;
        }
        if (doGelu) {
            o0.x = gelu_exact(o0.x); o0.y = gelu_exact(o0.y);
            o0.z = gelu_exact(o0.z); o0.w = gelu_exact(o0.w);
            o1.x = gelu_exact(o1.x); o1.y = gelu_exact(o1.y);
            o1.z = gelu_exact(o1.z); o1.w = gelu_exact(o1.w);
        }
        *(float4*)&Y[base + tx * 4] = o0;
        *(float4*)&Y[base + 64 + tx * 4] = o1;
    }
}

// ---------------- attention: warp per (b, voxel, head), time length 20 ----------------
__global__ void attn_kernel(const float* __restrict__ Q, const float* __restrict__ K,
                            const float* __restrict__ V, float* __restrict__ O) {
    __shared__ float sm[4][3][STOT][33];
    __shared__ float sat[4][STOT][21];
    int w = threadIdx.x >> 5, lane = threadIdx.x & 31;
    int unit = blockIdx.x * 4 + w;          // b*4096 + p*8 + h
    int h = unit & 7, p = (unit >> 3) & 511, b = unit >> 12;
    long base0 = ((long)(b * STOT) * NVOX + p) * E_ + h * HEAD_ + lane;
    float (*q)[33] = sm[w][0];
    float (*k)[33] = sm[w][1];
    float (*v)[33] = sm[w][2];
#pragma unroll
    for (int s = 0; s < STOT; s++) {
        long idx = base0 + (long)s * NVOX * E_;
        q[s][lane] = Q[idx]; k[s][lane] = K[idx]; v[s][lane] = V[idx];
    }
    __syncwarp();
    for (int pid = lane; pid < STOT * STOT; pid += 32) {
        int s = pid / STOT, t = pid % STOT;
        float d = 0.f;
#pragma unroll
        for (int dd = 0; dd < HEAD_; dd++) d += q[s][dd] * k[t][dd];
        sat[w][s][t] = d * 0.17677669529663689f;   // 1/sqrt(32)
    }
    __syncwarp();
    for (int s = 0; s < STOT; s++) {
        float x = (lane < STOT) ? sat[w][s][lane] : -1e30f;
        float m = x;
#pragma unroll
        for (int o2 = 16; o2; o2 >>= 1) m = fmaxf(m, __shfl_xor_sync(0xffffffffu, m, o2));
        float e = (lane < STOT) ? expf(x - m) : 0.f;
        float su = e;
#pragma unroll
        for (int o2 = 16; o2; o2 >>= 1) su += __shfl_xor_sync(0xffffffffu, su, o2);
        if (lane < STOT) sat[w][s][lane] = e / su;
    }
    __syncwarp();
    for (int s = 0; s < STOT; s++) {
        float a = 0.f;
#pragma unroll
        for (int t = 0; t < STOT; t++) a += sat[w][s][t] * v[t][lane];
        O[base0 + (long)s * NVOX * E_] = a;
    }
}

// ---------------- score / loss / argmax (warp per position) ----------------
__global__ void score_kernel(const float* __restrict__ LG, const int* __restrict__ ncode,
                             float* __restrict__ out) {
    int w    = (int)((blockIdx.x * (long)blockDim.x + threadIdx.x) >> 5);
    int lane = threadIdx.x & 31;
    if (w >= NB * PRED * NVOX) return;
    const float* row = LG + (long)w * NE_;
    float vals[16];
    float bv = -1e30f; int bi = 0x7fffffff;
#pragma unroll
    for (int i = 0; i < 16; i++) {
        vals[i] = row[lane + 32 * i];
        if (vals[i] > bv) { bv = vals[i]; bi = lane + 32 * i; }
    }
#pragma unroll
    for (int o = 16; o; o >>= 1) {
        float ov = __shfl_xor_sync(0xffffffffu, bv, o);
        int   oi = __shfl_xor_sync(0xffffffffu, bi, o);
        if (ov > bv || (ov == bv && oi < bi)) { bv = ov; bi = oi; }
    }
    float m = bv;
    float se = 0.f;
#pragma unroll
    for (int i = 0; i < 16; i++) se += expf(vals[i] - m);
#pragma unroll
    for (int o = 16; o; o >>= 1) se += __shfl_xor_sync(0xffffffffu, se, o);
    float logZ = m + logf(se);
    int b = w >> 11, t = (w >> 9) & 3, p = w & 511;
#pragma unroll
    for (int i = 0; i < 16; i++) {
        int c = lane + 32 * i;
        out[(long)(((b * NE_ + c) * PRED + t) * NVOX + p)] = vals[i];
    }
    if (lane == 0) {
        int tgt = ncode[w];
        g_LP[w] = row[tgt] - logZ;
        out[SCORE_ELEMS + 1 + w] = (float)bi;
    }
}

__global__ void finish_kernel(float* __restrict__ out) {
    __shared__ float sh[256];
    float s = 0.f;
    for (int i = threadIdx.x; i < NB * PRED * NVOX; i += 256) s += g_LP[i];
    sh[threadIdx.x] = s;
    __syncthreads();
    for (int o = 128; o; o >>= 1) {
        if (threadIdx.x < o) sh[threadIdx.x] += sh[threadIdx.x + o];
        __syncthreads();
    }
    if (threadIdx.x == 0) out[SCORE_ELEMS] = -sh[0] / (float)(NB * PRED * NVOX);
}

// ---------------- driver ----------------
extern "C" void kernel_launch(void* const* d_in, const int* in_sizes, int n_in,
                              void* d_out, int out_size) {
    const int*   code  = (const int*)d_in[0];
    const int*   ncode = (const int*)d_in[1];
    const float* emb   = (const float*)d_in[2];
    const float* pos   = (const float*)d_in[3];
    const float* ln1s  = (const float*)d_in[4];
    const float* ln1b  = (const float*)d_in[5];
    const float* ln2s  = (const float*)d_in[6];
    const float* ln2b  = (const float*)d_in[7];
    const float* wq = (const float*)d_in[8];  const float* bq = (const float*)d_in[9];
    const float* wk = (const float*)d_in[10]; const float* bk = (const float*)d_in[11];
    const float* wv = (const float*)d_in[12]; const float* bv = (const float*)d_in[13];
    const float* wo = (const float*)d_in[14]; const float* bo = (const float*)d_in[15];
    const float* w1 = (const float*)d_in[16]; const float* b1 = (const float*)d_in[17];
    const float* w2 = (const float*)d_in[18]; const float* b2 = (const float*)d_in[19];
    const float* lnfs = (const float*)d_in[20]; const float* lnfb = (const float*)d_in[21];
    const float* decw = (const float*)d_in[22]; const float* decb = (const float*)d_in[23];
    const float* declns = (const float*)d_in[24]; const float* declnb = (const float*)d_in[25];
    const float* linw = (const float*)d_in[26]; const float* linb = (const float*)d_in[27];
    float* out = (float*)d_out;

    float *X, *H, *Qb, *Kb, *Vb, *Ab, *HIDb, *XFb, *Y2b, *Y3b, *LGb;
    cudaGetSymbolAddress((void**)&X,   g_X);
    cudaGetSymbolAddress((void**)&H,   g_H);
    cudaGetSymbolAddress((void**)&Qb,  g_Q);
    cudaGetSymbolAddress((void**)&Kb,  g_K);
    cudaGetSymbolAddress((void**)&Vb,  g_V);
    cudaGetSymbolAddress((void**)&Ab,  g_A);
    cudaGetSymbolAddress((void**)&HIDb,g_HID);
    cudaGetSymbolAddress((void**)&XFb, g_XF);
    cudaGetSymbolAddress((void**)&Y2b, g_Y2);
    cudaGetSymbolAddress((void**)&Y3b, g_Y3);
    cudaGetSymbolAddress((void**)&LGb, g_LG);

    embed_kernel<<<40960, 256>>>(code, emb, pos, X);

    for (int i = 0; i < NL; i++) {
        const float* wq_i = wq + (long)i * 27 * E_ * E_;
        const float* wk_i = wk + (long)i * 27 * E_ * E_;
        const float* wv_i = wv + (long)i * 27 * E_ * E_;
        const float* wo_i = wo + (long)i * 27 * E_ * E_;
        const float* w1_i = w1 + (long)i * 27 * E_ * HID_;
        const float* w2_i = w2 + (long)i * 27 * HID_ * E_;

        ln_kernel<<<5120, 256>>>(X, H, ln1s + i * E_, ln1b + i * E_, NITEMS * NVOX, STOT, STOT, 0);
        conv_kernel<E_, E_, 27><<<dim3(NITEMS, 4, 2), 256>>>(H, wq_i, bq + i * E_, nullptr, Qb, STOT, STOT, 0, 0);
        conv_kernel<E_, E_, 27><<<dim3(NITEMS, 4, 2), 256>>>(H, wk_i, bk + i * E_, nullptr, Kb, STOT, STOT, 0, 0);
        conv_kernel<E_, E_, 27><<<dim3(NITEMS, 4, 2), 256>>>(H, wv_i, bv + i * E_, nullptr, Vb, STOT, STOT, 0, 0);
        attn_kernel<<<4096, 128>>>(Qb, Kb, Vb, Ab);
        conv_kernel<E_, E_, 27><<<dim3(NITEMS, 4, 2), 256>>>(Ab, wo_i, bo + i * E_, X, X, STOT, STOT, 0, 0);
        ln_kernel<<<5120, 256>>>(X, H, ln2s + i * E_, ln2b + i * E_, NITEMS * NVOX, STOT, STOT, 0);
        conv_kernel<E_, HID_, 27><<<dim3(NITEMS, 4, 4), 256>>>(H, w1_i, b1 + i * HID_, nullptr, HIDb, STOT, STOT, 0, 1);
        conv_kernel<HID_, E_, 27><<<dim3(NITEMS, 4, 2), 256>>>(HIDb, w2_i, b2 + i * E_, X, X, STOT, STOT, 0, 0);
    }

    // tail: only s >= BPTT is needed for the score
    ln_kernel<<<1024, 256>>>(X, XFb, lnfs, lnfb, NTAIL * NVOX, PRED, STOT, BPTT);
    conv_kernel<E_, E_, 27><<<dim3(NTAIL, 4, 2), 256>>>(XFb, decw, decb, nullptr, Y2b, PRED, PRED, 0, 1);
    ln_kernel<<<1024, 256>>>(Y2b, Y3b, declns, declnb, NTAIL * NVOX, PRED, PRED, 0);
    conv_kernel<E_, NE_, 1><<<dim3(NTAIL, 4, 4), 256>>>(Y3b, linw, linb, nullptr, LGb, PRED, PRED, 0, 0);
    score_kernel<<<1024, 256>>>(LGb, ncode, out);
    finish_kernel<<<1, 256>>>(out);
}

// round 6
// speedup vs baseline: 1.0650x; 1.0648x over previous
#include <cuda_runtime.h>
#include <math.h>
#include <stdint.h>

// ---------------- problem constants ----------------
#define NB   4
#define STOT 20
#define BPTT 16
#define PRED 4
#define NE_  512
#define E_   256
#define HID_ 512
#define NL   4
#define NVOX 512
#define NITEMS (NB*STOT)    // 80
#define NTAIL  (NB*PRED)    // 16
#define SCORE_ELEMS (NB*NE_*PRED*NVOX)   // 4194304

// ---------------- scratch ----------------
__device__ float g_X  [NITEMS*NVOX*E_];
__device__ float g_H  [NITEMS*NVOX*E_];
__device__ float g_Q  [NITEMS*NVOX*E_];
__device__ float g_K  [NITEMS*NVOX*E_];
__device__ float g_V  [NITEMS*NVOX*E_];
__device__ float g_A  [NITEMS*NVOX*E_];
__device__ float g_HID[NITEMS*NVOX*HID_];
__device__ float g_XF [NTAIL*NVOX*E_];
__device__ float g_Y2 [NTAIL*NVOX*E_];
__device__ float g_Y3 [NTAIL*NVOX*E_];
__device__ float g_LG [NTAIL*NVOX*NE_];
__device__ float g_LP [NB*PRED*NVOX];

// ---------------- f32x2 helpers (Blackwell packed fp32 FMA) ----------------
__device__ __forceinline__ unsigned long long pk2(float x, float y) {
    unsigned long long r;
    asm("mov.b64 %0, {%1, %2};" : "=l"(r) : "r"(__float_as_uint(x)), "r"(__float_as_uint(y)));
    return r;
}
__device__ __forceinline__ float2 upk2(unsigned long long v) {
    unsigned int lo, hi;
    asm("mov.b64 {%0, %1}, %2;" : "=r"(lo), "=r"(hi) : "l"(v));
    return make_float2(__uint_as_float(lo), __uint_as_float(hi));
}
__device__ __forceinline__ unsigned long long fma2(unsigned long long a, unsigned long long b,
                                                   unsigned long long c) {
    unsigned long long d;
    asm("fma.rn.f32x2 %0, %1, %2, %3;" : "=l"(d) : "l"(a), "l"(b), "l"(c));
    return d;
}
__device__ __forceinline__ float gelu_exact(float x) {
    return 0.5f * x * (1.0f + erff(x * 0.70710678118654752f));
}

// ---------------- embedding ----------------
__global__ void embed_kernel(const int* __restrict__ code, const float* __restrict__ emb,
                             const float* __restrict__ pos, float* __restrict__ X) {
    long idx = (long)blockIdx.x * 256 + threadIdx.x;
    int c  = (int)(idx & 255);
    int p  = (int)((idx >> 8) & 511);
    int ns = (int)(idx >> 17);
    int s  = ns % STOT;
    int b  = ns / STOT;
    int tok = (s < BPTT) ? code[(b * BPTT + s) * NVOX + p] : NE_;
    X[idx] = emb[tok * E_ + c] + pos[s * E_ + c];
}

// ---------------- layernorm (warp per row of 256); input item-mapped, output compact ----------------
__global__ void ln_kernel(const float* __restrict__ in, float* __restrict__ out,
                          const float* __restrict__ gam, const float* __restrict__ bet,
                          int rows, int s_count, int S_total, int s_off) {
    int w    = (int)((blockIdx.x * (long)blockDim.x + threadIdx.x) >> 5);
    int lane = threadIdx.x & 31;
    if (w >= rows) return;
    int n = w >> 9, p = w & 511;
    int bb = n / s_count, ss = s_off + n % s_count;
    const float* src = in + ((long)(bb * S_total + ss) * NVOX + p) * E_;
    float4 v0 = *(const float4*)&src[lane * 4];
    float4 v1 = *(const float4*)&src[128 + lane * 4];
    float s1 = v0.x + v0.y + v0.z + v0.w + v1.x + v1.y + v1.z + v1.w;
#pragma unroll
    for (int o = 16; o; o >>= 1) s1 += __shfl_xor_sync(0xffffffffu, s1, o);
    float m = s1 * (1.0f / 256.0f);
    float d0 = v0.x - m, d1 = v0.y - m, d2 = v0.z - m, d3 = v0.w - m;
    float d4 = v1.x - m, d5 = v1.y - m, d6 = v1.z - m, d7 = v1.w - m;
    float s2 = d0*d0 + d1*d1 + d2*d2 + d3*d3 + d4*d4 + d5*d5 + d6*d6 + d7*d7;
#pragma unroll
    for (int o = 16; o; o >>= 1) s2 += __shfl_xor_sync(0xffffffffu, s2, o);
    float r = rsqrtf(s2 * (1.0f / 256.0f) + 1e-5f);
    float4 g0 = *(const float4*)&gam[lane * 4];
    float4 g1 = *(const float4*)&gam[128 + lane * 4];
    float4 b0 = *(const float4*)&bet[lane * 4];
    float4 b1 = *(const float4*)&bet[128 + lane * 4];
    float* dst = out + (long)w * E_;
    *(float4*)&dst[lane * 4] =
        make_float4(d0*r*g0.x + b0.x, d1*r*g0.y + b0.y, d2*r*g0.z + b0.z, d3*r*g0.w + b0.w);
    *(float4*)&dst[128 + lane * 4] =
        make_float4(d4*r*g1.x + b1.x, d5*r*g1.y + b1.y, d6*r*g1.z + b1.z, d7*r*g1.w + b1.w);
}

// ---------------- conv3d as implicit GEMM (fp32 FFMA2, double-buffered) ----------------
// Item mapping: global_item = (n / sc)*St + so + n % sc  (identity when sc==St, so==0).
// Input uses (isc,iSt,iso); output + residual use (osc,oSt,oso).
template<int CIN, int COUT, int NOFF>
__global__ __launch_bounds__(256, 2)
void conv_kernel(const float* __restrict__ Xin, const float* __restrict__ W,
                 const float* __restrict__ bias, const float* __restrict__ Res,
                 float* __restrict__ Y,
                 int isc, int iSt, int iso, int osc, int oSt, int oso, int doGelu) {
    extern __shared__ float smem[];   // 2 stages x (As 32x132 | Bs 32x128) = 16640 floats
    const int n = blockIdx.x;
    const long in_base  = (long)((n / isc) * iSt + iso + n % isc) * NVOX * CIN;
    const long out_base = (long)((n / osc) * oSt + oso + n % osc) * NVOX * COUT;
    const int m0  = blockIdx.y * 128;
    const int co0 = blockIdx.z * 128;
    const int tid = threadIdx.x;
    const int ty = tid >> 4, tx = tid & 15;
    const int av = tid >> 3;          // A-load row base (0..31)
    const int ak = (tid & 7) * 4;     // A-load k offset
    const int bk0 = tid >> 5;         // B-load k base (0..7)
    const int bc  = (tid & 31) * 4;   // B-load co offset
    constexpr int CK = CIN / 32;
    constexpr int NCH = NOFF * CK;

    unsigned long long acc[8][4];
#pragma unroll
    for (int i = 0; i < 8; i++)
#pragma unroll
        for (int j = 0; j < 4; j++) acc[i][j] = 0ull;

    float4 ra[4], rb[4];

    auto load_g = [&](int c) {
        const int o = c / CK, kc = (c % CK) * 32;
        int da = 0, db = 0, dc = 0;
        if (NOFF == 27) { da = o / 9 - 1; db = (o / 3) % 3 - 1; dc = o % 3 - 1; }
#pragma unroll
        for (int it = 0; it < 4; ++it) {
            int v = it * 32 + av;
            int vox = m0 + v;
            int j0 = (vox >> 6) + da, j1 = ((vox >> 3) & 7) + db, j2 = (vox & 7) + dc;
            bool ok = (NOFF == 1) ||
                      (((unsigned)j0 < 8u) && ((unsigned)j1 < 8u) && ((unsigned)j2 < 8u));
            ra[it] = ok ? *(const float4*)&Xin[in_base + (long)((j0 << 6) + (j1 << 3) + j2) * CIN + kc + ak]
                        : make_float4(0.f, 0.f, 0.f, 0.f);
        }
        const float* Wo = W + ((long)o * CIN + kc) * COUT + co0;
#pragma unroll
        for (int it = 0; it < 4; ++it)
            rb[it] = *(const float4*)&Wo[(long)(it * 8 + bk0) * COUT + bc];
    };
    auto store_s = [&](int st) {
        float* As = smem + st * 8320;
        float* Bs = As + 4224;
#pragma unroll
        for (int it = 0; it < 4; ++it) {
            int v = it * 32 + av;
            As[(ak + 0) * 132 + v] = ra[it].x;
            As[(ak + 1) * 132 + v] = ra[it].y;
            As[(ak + 2) * 132 + v] = ra[it].z;
            As[(ak + 3) * 132 + v] = ra[it].w;
        }
#pragma unroll
        for (int it = 0; it < 4; ++it)
            *(float4*)&Bs[(it * 8 + bk0) * 128 + bc] = rb[it];
    };

    load_g(0);
    store_s(0);
    __syncthreads();

    for (int c = 0; c < NCH; ++c) {
        const int st = c & 1;
        if (c + 1 < NCH) load_g(c + 1);
        const float* As = smem + st * 8320;
        const float* Bs = As + 4224;
#pragma unroll
        for (int kk = 0; kk < 32; ++kk) {
            float4 a0 = *(const float4*)&As[kk * 132 + ty * 4];
            float4 a1 = *(const float4*)&As[kk * 132 + 64 + ty * 4];
            float4 b0 = *(const float4*)&Bs[kk * 128 + tx * 4];
            float4 b1 = *(const float4*)&Bs[kk * 128 + 64 + tx * 4];
            unsigned long long bp0 = pk2(b0.x, b0.y), bp1 = pk2(b0.z, b0.w);
            unsigned long long bp2 = pk2(b1.x, b1.y), bp3 = pk2(b1.z, b1.w);
            float am[8] = {a0.x, a0.y, a0.z, a0.w, a1.x, a1.y, a1.z, a1.w};
#pragma unroll
            for (int i = 0; i < 8; i++) {
                unsigned long long ap = pk2(am[i], am[i]);
                acc[i][0] = fma2(ap, bp0, acc[i][0]);
                acc[i][1] = fma2(ap, bp1, acc[i][1]);
                acc[i][2] = fma2(ap, bp2, acc[i][2]);
                acc[i][3] = fma2(ap, bp3, acc[i][3]);
            }
        }
        if (c + 1 < NCH) store_s(st ^ 1);
        __syncthreads();
    }

    float4 bias0 = *(const float4*)&bias[co0 + tx * 4];
    float4 bias1 = *(const float4*)&bias[co0 + 64 + tx * 4];
#pragma unroll
    for (int i = 0; i < 8; i++) {
        int r = (i < 4) ? (ty * 4 + i) : (64 + ty * 4 + i - 4);
        long base = out_base + (long)(m0 + r) * COUT + co0;
        float2 p0 = upk2(acc[i][0]), p1 = upk2(acc[i][1]);
        float2 p2 = upk2(acc[i][2]), p3 = upk2(acc[i][3]);
        float4 o0 = make_float4(p0.x + bias0.x, p0.y + bias0.y, p1.x + bias0.z, p1.y + bias0.w);
        float4 o1 = make_float4(p2.x + bias1.x, p2.y + bias1.y, p3.x + bias1.z, p3.y + bias1.w);
        if (Res) {
            float4 r0 = *(const float4*)&Res[base + tx * 4];
            float4 r1 = *(const float4*)&Res[base + 64 + tx * 4];
            o0.x += r0.x; o0.y += r0.y; o0.z += r0.z; o0.w += r0.w;
            o1.x += r1.x; o1.y += r1.y; o1.z += r1.z; o1.w += r1.w;
        }
        if (doGelu) {
            o0.x = gelu_exact(o0.x); o0.y = gelu_exact(o0.y);
            o0.z = gelu_exact(o0.z); o0.w = gelu_exact(o0.w);
            o1.x = gelu_exact(o1.x); o1.y = gelu_exact(o1.y);
            o1.z = gelu_exact(o1.z); o1.w = gelu_exact(o1.w);
        }
        *(float4*)&Y[base + tx * 4] = o0;
        *(float4*)&Y[base + 64 + tx * 4] = o1;
    }
}

// ---------------- attention ----------------
__global__ void attn_kernel(const float* __restrict__ Q, const float* __restrict__ K,
                            const float* __restrict__ V, float* __restrict__ O) {
    __shared__ float sm[4][3][STOT][33];
    __shared__ float sat[4][STOT][21];
    int w = threadIdx.x >> 5, lane = threadIdx.x & 31;
    int unit = blockIdx.x * 4 + w;
    int h = unit & 7, p = (unit >> 3) & 511, b = unit >> 12;
    long base0 = ((long)(b * STOT) * NVOX + p) * E_ + h * 32 + lane;
    float (*q)[33] = sm[w][0];
    float (*k)[33] = sm[w][1];
    float (*v)[33] = sm[w][2];
#pragma unroll
    for (int s = 0; s < STOT; s++) {
        long idx = base0 + (long)s * NVOX * E_;
        q[s][lane] = Q[idx]; k[s][lane] = K[idx]; v[s][lane] = V[idx];
    }
    __syncwarp();
    for (int pid = lane; pid < STOT * STOT; pid += 32) {
        int s = pid / STOT, t = pid % STOT;
        float d = 0.f;
#pragma unroll
        for (int dd = 0; dd < 32; dd++) d += q[s][dd] * k[t][dd];
        sat[w][s][t] = d * 0.17677669529663689f;
    }
    __syncwarp();
    for (int s = 0; s < STOT; s++) {
        float x = (lane < STOT) ? sat[w][s][lane] : -1e30f;
        float m = x;
#pragma unroll
        for (int o2 = 16; o2; o2 >>= 1) m = fmaxf(m, __shfl_xor_sync(0xffffffffu, m, o2));
        float e = (lane < STOT) ? expf(x - m) : 0.f;
        float su = e;
#pragma unroll
        for (int o2 = 16; o2; o2 >>= 1) su += __shfl_xor_sync(0xffffffffu, su, o2);
        if (lane < STOT) sat[w][s][lane] = e / su;
    }
    __syncwarp();
    for (int s = 0; s < STOT; s++) {
        float a = 0.f;
#pragma unroll
        for (int t = 0; t < STOT; t++) a += sat[w][s][t] * v[t][lane];
        O[base0 + (long)s * NVOX * E_] = a;
    }
}

// ---------------- score / loss / argmax ----------------
__global__ void score_kernel(const float* __restrict__ LG, const int* __restrict__ ncode,
                             float* __restrict__ out) {
    int w    = (int)((blockIdx.x * (long)blockDim.x + threadIdx.x) >> 5);
    int lane = threadIdx.x & 31;
    if (w >= NB * PRED * NVOX) return;
    const float* row = LG + (long)w * NE_;
    float vals[16];
    float bv = -1e30f; int bi = 0x7fffffff;
#pragma unroll
    for (int i = 0; i < 16; i++) {
        vals[i] = row[lane + 32 * i];
        if (vals[i] > bv) { bv = vals[i]; bi = lane + 32 * i; }
    }
#pragma unroll
    for (int o = 16; o; o >>= 1) {
        float ov = __shfl_xor_sync(0xffffffffu, bv, o);
        int   oi = __shfl_xor_sync(0xffffffffu, bi, o);
        if (ov > bv || (ov == bv && oi < bi)) { bv = ov; bi = oi; }
    }
    float m = bv;
    float se = 0.f;
#pragma unroll
    for (int i = 0; i < 16; i++) se += expf(vals[i] - m);
#pragma unroll
    for (int o = 16; o; o >>= 1) se += __shfl_xor_sync(0xffffffffu, se, o);
    float logZ = m + logf(se);
    int b = w >> 11, t = (w >> 9) & 3, p = w & 511;
#pragma unroll
    for (int i = 0; i < 16; i++) {
        int c = lane + 32 * i;
        out[(long)(((b * NE_ + c) * PRED + t) * NVOX + p)] = vals[i];
    }
    if (lane == 0) {
        g_LP[w] = row[ncode[w]] - logZ;
        out[SCORE_ELEMS + 1 + w] = (float)bi;
    }
}

__global__ void finish_kernel(float* __restrict__ out) {
    __shared__ float sh[256];
    float s = 0.f;
    for (int i = threadIdx.x; i < NB * PRED * NVOX; i += 256) s += g_LP[i];
    sh[threadIdx.x] = s;
    __syncthreads();
    for (int o = 128; o; o >>= 1) {
        if (threadIdx.x < o) sh[threadIdx.x] += sh[threadIdx.x + o];
        __syncthreads();
    }
    if (threadIdx.x == 0) out[SCORE_ELEMS] = -sh[0] / (float)(NB * PRED * NVOX);
}

#define CONV_SMEM (16640 * 4)   // 66560 bytes, 2 stages

// ---------------- driver ----------------
extern "C" void kernel_launch(void* const* d_in, const int* in_sizes, int n_in,
                              void* d_out, int out_size) {
    const int*   code  = (const int*)d_in[0];
    const int*   ncode = (const int*)d_in[1];
    const float* emb   = (const float*)d_in[2];
    const float* pos   = (const float*)d_in[3];
    const float* ln1s  = (const float*)d_in[4];
    const float* ln1b  = (const float*)d_in[5];
    const float* ln2s  = (const float*)d_in[6];
    const float* ln2b  = (const float*)d_in[7];
    const float* wq = (const float*)d_in[8];  const float* bq = (const float*)d_in[9];
    const float* wk = (const float*)d_in[10]; const float* bk = (const float*)d_in[11];
    const float* wv = (const float*)d_in[12]; const float* bv = (const float*)d_in[13];
    const float* wo = (const float*)d_in[14]; const float* bo = (const float*)d_in[15];
    const float* w1 = (const float*)d_in[16]; const float* b1 = (const float*)d_in[17];
    const float* w2 = (const float*)d_in[18]; const float* b2 = (const float*)d_in[19];
    const float* lnfs = (const float*)d_in[20]; const float* lnfb = (const float*)d_in[21];
    const float* decw = (const float*)d_in[22]; const float* decb = (const float*)d_in[23];
    const float* declns = (const float*)d_in[24]; const float* declnb = (const float*)d_in[25];
    const float* linw = (const float*)d_in[26]; const float* linb = (const float*)d_in[27];
    float* out = (float*)d_out;

    float *X, *H, *Qb, *Kb, *Vb, *Ab, *HIDb, *XFb, *Y2b, *Y3b, *LGb;
    cudaGetSymbolAddress((void**)&X,   g_X);
    cudaGetSymbolAddress((void**)&H,   g_H);
    cudaGetSymbolAddress((void**)&Qb,  g_Q);
    cudaGetSymbolAddress((void**)&Kb,  g_K);
    cudaGetSymbolAddress((void**)&Vb,  g_V);
    cudaGetSymbolAddress((void**)&Ab,  g_A);
    cudaGetSymbolAddress((void**)&HIDb,g_HID);
    cudaGetSymbolAddress((void**)&XFb, g_XF);
    cudaGetSymbolAddress((void**)&Y2b, g_Y2);
    cudaGetSymbolAddress((void**)&Y3b, g_Y3);
    cudaGetSymbolAddress((void**)&LGb, g_LG);

    cudaFuncSetAttribute(conv_kernel<256,256,27>, cudaFuncAttributeMaxDynamicSharedMemorySize, CONV_SMEM);
    cudaFuncSetAttribute(conv_kernel<256,512,27>, cudaFuncAttributeMaxDynamicSharedMemorySize, CONV_SMEM);
    cudaFuncSetAttribute(conv_kernel<512,256,27>, cudaFuncAttributeMaxDynamicSharedMemorySize, CONV_SMEM);
    cudaFuncSetAttribute(conv_kernel<256,512,1>,  cudaFuncAttributeMaxDynamicSharedMemorySize, CONV_SMEM);

    embed_kernel<<<40960, 256>>>(code, emb, pos, X);

    for (int i = 0; i < NL; i++) {
        const float* wq_i = wq + (long)i * 27 * E_ * E_;
        const float* wk_i = wk + (long)i * 27 * E_ * E_;
        const float* wv_i = wv + (long)i * 27 * E_ * E_;
        const float* wo_i = wo + (long)i * 27 * E_ * E_;
        const float* w1_i = w1 + (long)i * 27 * E_ * HID_;
        const float* w2_i = w2 + (long)i * 27 * HID_ * E_;

        ln_kernel<<<5120, 256>>>(X, H, ln1s + i * E_, ln1b + i * E_, NITEMS * NVOX, STOT, STOT, 0);
        conv_kernel<E_, E_, 27><<<dim3(NITEMS, 4, 2), 256, CONV_SMEM>>>(
            H, wq_i, bq + i * E_, nullptr, Qb, STOT, STOT, 0, STOT, STOT, 0, 0);
        conv_kernel<E_, E_, 27><<<dim3(NITEMS, 4, 2), 256, CONV_SMEM>>>(
            H, wk_i, bk + i * E_, nullptr, Kb, STOT, STOT, 0, STOT, STOT, 0, 0);
        conv_kernel<E_, E_, 27><<<dim3(NITEMS, 4, 2), 256, CONV_SMEM>>>(
            H, wv_i, bv + i * E_, nullptr, Vb, STOT, STOT, 0, STOT, STOT, 0, 0);
        attn_kernel<<<4096, 128>>>(Qb, Kb, Vb, Ab);

        if (i < NL - 1) {
            conv_kernel<E_, E_, 27><<<dim3(NITEMS, 4, 2), 256, CONV_SMEM>>>(
                Ab, wo_i, bo + i * E_, X, X, STOT, STOT, 0, STOT, STOT, 0, 0);
            ln_kernel<<<5120, 256>>>(X, H, ln2s + i * E_, ln2b + i * E_, NITEMS * NVOX, STOT, STOT, 0);
            conv_kernel<E_, HID_, 27><<<dim3(NITEMS, 4, 4), 256, CONV_SMEM>>>(
                H, w1_i, b1 + i * HID_, nullptr, HIDb, STOT, STOT, 0, STOT, STOT, 0, 1);
            conv_kernel<HID_, E_, 27><<<dim3(NITEMS, 4, 2), 256, CONV_SMEM>>>(
                HIDb, w2_i, b2 + i * E_, X, X, STOT, STOT, 0, STOT, STOT, 0, 0);
        } else {
            // layer 4: only s >= BPTT feeds the output
            conv_kernel<E_, E_, 27><<<dim3(NTAIL, 4, 2), 256, CONV_SMEM>>>(
                Ab, wo_i, bo + i * E_, X, X, PRED, STOT, BPTT, PRED, STOT, BPTT, 0);
            ln_kernel<<<1024, 256>>>(X, H, ln2s + i * E_, ln2b + i * E_, NTAIL * NVOX, PRED, STOT, BPTT);
            conv_kernel<E_, HID_, 27><<<dim3(NTAIL, 4, 4), 256, CONV_SMEM>>>(
                H, w1_i, b1 + i * HID_, nullptr, HIDb, PRED, PRED, 0, PRED, PRED, 0, 1);
            conv_kernel<HID_, E_, 27><<<dim3(NTAIL, 4, 2), 256, CONV_SMEM>>>(
                HIDb, w2_i, b2 + i * E_, X, X, PRED, PRED, 0, PRED, STOT, BPTT, 0);
        }
    }

    // tail: only s >= BPTT
    ln_kernel<<<1024, 256>>>(X, XFb, lnfs, lnfb, NTAIL * NVOX, PRED, STOT, BPTT);
    conv_kernel<E_, E_, 27><<<dim3(NTAIL, 4, 2), 256, CONV_SMEM>>>(
        XFb, decw, decb, nullptr, Y2b, PRED, PRED, 0, PRED, PRED, 0, 1);
    ln_kernel<<<1024, 256>>>(Y2b, Y3b, declns, declnb, NTAIL * NVOX, PRED, PRED, 0);
    conv_kernel<E_, NE_, 1><<<dim3(NTAIL, 4, 4), 256, CONV_SMEM>>>(
        Y3b, linw, linb, nullptr, LGb, PRED, PRED, 0, PRED, PRED, 0, 0);
    score_kernel<<<1024, 256>>>(LGb, ncode, out);
    finish_kernel<<<1, 256>>>(out);
}

// round 9
// speedup vs baseline: 3.4717x; 3.2598x over previous
#include <cuda_runtime.h>
#include <math.h>
#include <stdint.h>

#define NB 4
#define STOT 20
#define BPTT 16
#define PRED 4
#define NE_ 512
#define E_ 256
#define HID_ 512
#define NL 4
#define NVOX 512
#define NITEMS (NB*STOT)
#define NTAIL (NB*PRED)
#define SCORE_ELEMS (NB*NE_*PRED*NVOX)

// ---------------- scratch ----------------
__device__ float g_X  [NITEMS*NVOX*E_];
__device__ float g_H  [NITEMS*NVOX*E_];
__device__ float g_Q  [NITEMS*NVOX*E_];
__device__ float g_K  [NITEMS*NVOX*E_];
__device__ float g_V  [NITEMS*NVOX*E_];
__device__ float g_A  [NITEMS*NVOX*E_];
__device__ float g_HID[NITEMS*NVOX*HID_];
__device__ float g_XF [NTAIL*NVOX*E_];
__device__ float g_Y2 [NTAIL*NVOX*E_];
__device__ float g_Y3 [NTAIL*NVOX*E_];
__device__ float g_LG [NTAIL*NVOX*NE_];
__device__ float g_LP [NB*PRED*NVOX];
// Winograd scratch
__device__ float g_WV [64L*5120*512];   // input transforms  [p][tile][ci]
__device__ float g_WM [64L*5120*512];   // gemm outputs      [p][tile][co]
__device__ float g_WU [64L*512*256];    // weight transforms [p][ci][co] (max 64*131072)

// ---------------- f32x2 helpers ----------------
__device__ __forceinline__ unsigned long long pk2(float x, float y) {
    unsigned long long r;
    asm("mov.b64 %0, {%1, %2};" : "=l"(r) : "r"(__float_as_uint(x)), "r"(__float_as_uint(y)));
    return r;
}
__device__ __forceinline__ float2 upk2(unsigned long long v) {
    unsigned int lo, hi;
    asm("mov.b64 {%0, %1}, %2;" : "=r"(lo), "=r"(hi) : "l"(v));
    return make_float2(__uint_as_float(lo), __uint_as_float(hi));
}
__device__ __forceinline__ unsigned long long fma2(unsigned long long a, unsigned long long b,
                                                   unsigned long long c) {
    unsigned long long d;
    asm("fma.rn.f32x2 %0, %1, %2, %3;" : "=l"(d) : "l"(a), "l"(b), "l"(c));
    return d;
}
__device__ __forceinline__ float gelu_exact(float x) {
    return 0.5f * x * (1.0f + erff(x * 0.70710678118654752f));
}

// ---------------- embedding ----------------
__global__ void embed_kernel(const int* __restrict__ code, const float* __restrict__ emb,
                             const float* __restrict__ pos, float* __restrict__ X) {
    long idx = (long)blockIdx.x * 256 + threadIdx.x;
    int c = (int)(idx & 255), p = (int)((idx >> 8) & 511), ns = (int)(idx >> 17);
    int s = ns % STOT, b = ns / STOT;
    int tok = (s < BPTT) ? code[(b * BPTT + s) * NVOX + p] : NE_;
    X[idx] = emb[tok * E_ + c] + pos[s * E_ + c];
}

// ---------------- layernorm: input item-mapped, output compact ----------------
__global__ void ln_kernel(const float* __restrict__ in, float* __restrict__ out,
                          const float* __restrict__ gam, const float* __restrict__ bet,
                          int rows, int s_count, int S_total, int s_off) {
    int w = (int)((blockIdx.x * (long)blockDim.x + threadIdx.x) >> 5);
    int lane = threadIdx.x & 31;
    if (w >= rows) return;
    int n = w >> 9, p = w & 511;
    int bb = n / s_count, ss = s_off + n % s_count;
    const float* src = in + ((long)(bb * S_total + ss) * NVOX + p) * E_;
    float4 v0 = *(const float4*)&src[lane * 4];
    float4 v1 = *(const float4*)&src[128 + lane * 4];
    float s1 = v0.x + v0.y + v0.z + v0.w + v1.x + v1.y + v1.z + v1.w;
#pragma unroll
    for (int o = 16; o; o >>= 1) s1 += __shfl_xor_sync(0xffffffffu, s1, o);
    float m = s1 * (1.0f / 256.0f);
    float d0 = v0.x-m, d1 = v0.y-m, d2 = v0.z-m, d3 = v0.w-m;
    float d4 = v1.x-m, d5 = v1.y-m, d6 = v1.z-m, d7 = v1.w-m;
    float s2 = d0*d0+d1*d1+d2*d2+d3*d3+d4*d4+d5*d5+d6*d6+d7*d7;
#pragma unroll
    for (int o = 16; o; o >>= 1) s2 += __shfl_xor_sync(0xffffffffu, s2, o);
    float r = rsqrtf(s2 * (1.0f / 256.0f) + 1e-5f);
    float4 g0 = *(const float4*)&gam[lane*4], g1 = *(const float4*)&gam[128+lane*4];
    float4 b0 = *(const float4*)&bet[lane*4], b1 = *(const float4*)&bet[128+lane*4];
    float* dst = out + (long)w * E_;
    *(float4*)&dst[lane*4]     = make_float4(d0*r*g0.x+b0.x, d1*r*g0.y+b0.y, d2*r*g0.z+b0.z, d3*r*g0.w+b0.w);
    *(float4*)&dst[128+lane*4] = make_float4(d4*r*g1.x+b1.x, d5*r*g1.y+b1.y, d6*r*g1.z+b1.z, d7*r*g1.w+b1.w);
}

// ---------------- Winograd input transform: V = B^T d B (3D) ----------------
// grid: nitems*64, 256 threads (loop over ci)
template<int CI>
__global__ void wg_intrans(const float* __restrict__ X, float* __restrict__ V,
                           int nitems, int isc, int iSt, int iso) {
    int blk = blockIdx.x;
    int item = blk >> 6, tile = blk & 63;
    int t0 = tile >> 4, t1 = (tile >> 2) & 3, t2 = tile & 3;
    long gitem = (long)(item / isc) * iSt + iso + item % isc;
    const float* src = X + gitem * NVOX * CI;
    const int NT = nitems * 64;
    const long NTCI = (long)NT * CI;
    for (int ci = threadIdx.x; ci < CI; ci += 256) {
        float d[4][4][4];
#pragma unroll
        for (int i = 0; i < 4; i++) {
            int j0 = 2 * t0 - 1 + i;
#pragma unroll
            for (int j = 0; j < 4; j++) {
                int j1 = 2 * t1 - 1 + j;
#pragma unroll
                for (int k = 0; k < 4; k++) {
                    int j2 = 2 * t2 - 1 + k;
                    bool ok = ((unsigned)j0 < 8u) && ((unsigned)j1 < 8u) && ((unsigned)j2 < 8u);
                    d[i][j][k] = ok ? src[(long)((j0 << 6) + (j1 << 3) + j2) * CI + ci] : 0.f;
                }
            }
        }
#pragma unroll
        for (int i = 0; i < 4; i++)
#pragma unroll
            for (int j = 0; j < 4; j++) {
                float A = d[i][j][0], B = d[i][j][1], C = d[i][j][2], D = d[i][j][3];
                d[i][j][0] = A - C; d[i][j][1] = B + C; d[i][j][2] = C - B; d[i][j][3] = B - D;
            }
#pragma unroll
        for (int i = 0; i < 4; i++)
#pragma unroll
            for (int k = 0; k < 4; k++) {
                float A = d[i][0][k], B = d[i][1][k], C = d[i][2][k], D = d[i][3][k];
                d[i][0][k] = A - C; d[i][1][k] = B + C; d[i][2][k] = C - B; d[i][3][k] = B - D;
            }
#pragma unroll
        for (int j = 0; j < 4; j++)
#pragma unroll
            for (int k = 0; k < 4; k++) {
                float A = d[0][j][k], B = d[1][j][k], C = d[2][j][k], D = d[3][j][k];
                d[0][j][k] = A - C; d[1][j][k] = B + C; d[2][j][k] = C - B; d[3][j][k] = B - D;
            }
        long base = (long)(item * 64 + tile) * CI + ci;
#pragma unroll
        for (int p = 0; p < 64; p++)
            V[(long)p * NTCI + base] = d[p >> 4][(p >> 2) & 3][p & 3];
    }
}

// ---------------- Winograd weight transform: U = G g G^T (3D) ----------------
// grid: CI, 256 threads (loop over co). W layout [o][ci][co] -> U [p][ci][co]
__global__ void wg_wtrans(const float* __restrict__ W, float* __restrict__ U, int CI, int CO) {
    int ci = blockIdx.x;
    for (int co = threadIdx.x; co < CO; co += 256) {
        float g[3][3][3];
#pragma unroll
        for (int o = 0; o < 27; o++)
            g[o / 9][(o / 3) % 3][o % 3] = W[((long)o * CI + ci) * CO + co];
        float u[4][4][4];
#pragma unroll
        for (int i = 0; i < 3; i++)
#pragma unroll
            for (int j = 0; j < 3; j++) {
                float a = g[i][j][0], b = g[i][j][1], c = g[i][j][2];
                u[i][j][0] = a; u[i][j][1] = 0.5f*(a+b+c); u[i][j][2] = 0.5f*(a-b+c); u[i][j][3] = c;
            }
#pragma unroll
        for (int i = 0; i < 3; i++)
#pragma unroll
            for (int k = 0; k < 4; k++) {
                float a = u[i][0][k], b = u[i][1][k], c = u[i][2][k];
                u[i][0][k] = a; u[i][1][k] = 0.5f*(a+b+c); u[i][2][k] = 0.5f*(a-b+c); u[i][3][k] = c;
            }
#pragma unroll
        for (int j = 0; j < 4; j++)
#pragma unroll
            for (int k = 0; k < 4; k++) {
                float a = u[0][j][k], b = u[1][j][k], c = u[2][j][k];
                u[0][j][k] = a; u[1][j][k] = 0.5f*(a+b+c); u[2][j][k] = 0.5f*(a-b+c); u[3][j][k] = c;
            }
#pragma unroll
        for (int p = 0; p < 64; p++)
            U[((long)p * CI + ci) * CO + co] = u[p >> 4][(p >> 2) & 3][p & 3];
    }
}

// ---------------- batched point-GEMM (fp32 FFMA2, proven core) ----------------
// grid (64 points, NT/128, CO/128). M[p][row][co] = sum_k V[p][row][k] * U[p][k][co]
template<int CIN, int COUT>
__global__ __launch_bounds__(256, 2)
void wg_gemm(const float* __restrict__ V, const float* __restrict__ U,
             float* __restrict__ M, int NT) {
    extern __shared__ float smem[];
    const int p = blockIdx.x;
    const int m0 = blockIdx.y * 128, co0 = blockIdx.z * 128;
    const float* Abase = V + ((long)p * NT + m0) * CIN;
    const float* Bbase = U + (long)p * CIN * COUT + co0;
    float* Obase = M + ((long)p * NT + m0) * COUT + co0;
    const int tid = threadIdx.x;
    const int ty = tid >> 4, tx = tid & 15;
    const int av = tid >> 3, ak = (tid & 7) * 4;
    const int bk0 = tid >> 5, bc = (tid & 31) * 4;
    constexpr int NCH = CIN / 32;

    unsigned long long acc[8][4];
#pragma unroll
    for (int i = 0; i < 8; i++)
#pragma unroll
        for (int j = 0; j < 4; j++) acc[i][j] = 0ull;

    float4 ra[4], rb[4];
    auto load_g = [&](int c) {
        int kc = c * 32;
#pragma unroll
        for (int it = 0; it < 4; ++it)
            ra[it] = *(const float4*)&Abase[(long)(it * 32 + av) * CIN + kc + ak];
#pragma unroll
        for (int it = 0; it < 4; ++it)
            rb[it] = *(const float4*)&Bbase[(long)(kc + it * 8 + bk0) * COUT + bc];
    };
    auto store_s = [&](int st) {
        float* As = smem + st * 8320;
        float* Bs = As + 4224;
#pragma unroll
        for (int it = 0; it < 4; ++it) {
            int v = it * 32 + av;
            As[(ak + 0) * 132 + v] = ra[it].x;
            As[(ak + 1) * 132 + v] = ra[it].y;
            As[(ak + 2) * 132 + v] = ra[it].z;
            As[(ak + 3) * 132 + v] = ra[it].w;
        }
#pragma unroll
        for (int it = 0; it < 4; ++it)
            *(float4*)&Bs[(it * 8 + bk0) * 128 + bc] = rb[it];
    };

    load_g(0);
    store_s(0);
    __syncthreads();
    for (int c = 0; c < NCH; ++c) {
        const int st = c & 1;
        if (c + 1 < NCH) load_g(c + 1);
        const float* As = smem + st * 8320;
        const float* Bs = As + 4224;
#pragma unroll
        for (int kk = 0; kk < 32; ++kk) {
            float4 a0 = *(const float4*)&As[kk * 132 + ty * 4];
            float4 a1 = *(const float4*)&As[kk * 132 + 64 + ty * 4];
            float4 b0 = *(const float4*)&Bs[kk * 128 + tx * 4];
            float4 b1 = *(const float4*)&Bs[kk * 128 + 64 + tx * 4];
            unsigned long long bp0 = pk2(b0.x, b0.y), bp1 = pk2(b0.z, b0.w);
            unsigned long long bp2 = pk2(b1.x, b1.y), bp3 = pk2(b1.z, b1.w);
            float am[8] = {a0.x, a0.y, a0.z, a0.w, a1.x, a1.y, a1.z, a1.w};
#pragma unroll
            for (int i = 0; i < 8; i++) {
                unsigned long long ap = pk2(am[i], am[i]);
                acc[i][0] = fma2(ap, bp0, acc[i][0]);
                acc[i][1] = fma2(ap, bp1, acc[i][1]);
                acc[i][2] = fma2(ap, bp2, acc[i][2]);
                acc[i][3] = fma2(ap, bp3, acc[i][3]);
            }
        }
        if (c + 1 < NCH) store_s(st ^ 1);
        __syncthreads();
    }
#pragma unroll
    for (int i = 0; i < 8; i++) {
        int r = (i < 4) ? (ty * 4 + i) : (64 + ty * 4 + i - 4);
        float2 p0 = upk2(acc[i][0]), p1 = upk2(acc[i][1]);
        float2 p2 = upk2(acc[i][2]), p3 = upk2(acc[i][3]);
        *(float4*)&Obase[(long)r * COUT + tx * 4]      = make_float4(p0.x, p0.y, p1.x, p1.y);
        *(float4*)&Obase[(long)r * COUT + 64 + tx * 4] = make_float4(p2.x, p2.y, p3.x, p3.y);
    }
}

// ---------------- Winograd output transform: Y = A^T M A (3D) + epilogue ----------------
// grid: nitems*64, 256 threads (loop co). EPI: 0 none, 1 residual, 2 gelu
template<int EPI>
__global__ void wg_outtrans(const float* __restrict__ M, const float* __restrict__ bias,
                            const float* __restrict__ Res, float* __restrict__ Y,
                            int CO, int nitems, int osc, int oSt, int oso) {
    int blk = blockIdx.x;
    int item = blk >> 6, tile = blk & 63;
    int t0 = tile >> 4, t1 = (tile >> 2) & 3, t2 = tile & 3;
    long gout = (long)(item / osc) * oSt + oso + item % osc;
    const int NT = nitems * 64;
    const long NTCO = (long)NT * CO;
    for (int co = threadIdx.x; co < CO; co += 256) {
        float m[4][4][4];
        long base = (long)(item * 64 + tile) * CO + co;
#pragma unroll
        for (int p = 0; p < 64; p++)
            m[p >> 4][(p >> 2) & 3][p & 3] = M[(long)p * NTCO + base];
        float a[4][4][2];
#pragma unroll
        for (int i = 0; i < 4; i++)
#pragma unroll
            for (int j = 0; j < 4; j++) {
                a[i][j][0] = m[i][j][0] + m[i][j][1] + m[i][j][2];
                a[i][j][1] = m[i][j][1] - m[i][j][2] - m[i][j][3];
            }
        float b2[4][2][2];
#pragma unroll
        for (int i = 0; i < 4; i++)
#pragma unroll
            for (int k = 0; k < 2; k++) {
                b2[i][0][k] = a[i][0][k] + a[i][1][k] + a[i][2][k];
                b2[i][1][k] = a[i][1][k] - a[i][2][k] - a[i][3][k];
            }
        float bv = bias[co];
#pragma unroll
        for (int j = 0; j < 2; j++)
#pragma unroll
            for (int k = 0; k < 2; k++) {
                float y0 = b2[0][j][k] + b2[1][j][k] + b2[2][j][k];
                float y1 = b2[1][j][k] - b2[2][j][k] - b2[3][j][k];
#pragma unroll
                for (int i = 0; i < 2; i++) {
                    float v = (i == 0 ? y0 : y1) + bv;
                    int vox = (((2 * t0 + i) << 6) + ((2 * t1 + j) << 3) + (2 * t2 + k));
                    long oidx = (gout * NVOX + vox) * CO + co;
                    if (EPI == 1) v += Res[oidx];
                    if (EPI == 2) v = gelu_exact(v);
                    Y[oidx] = v;
                }
            }
    }
}

// ---------------- attention ----------------
__global__ void attn_kernel(const float* __restrict__ Q, const float* __restrict__ K,
                            const float* __restrict__ V, float* __restrict__ O) {
    __shared__ float sm[4][3][STOT][33];
    __shared__ float sat[4][STOT][21];
    int w = threadIdx.x >> 5, lane = threadIdx.x & 31;
    int unit = blockIdx.x * 4 + w;
    int h = unit & 7, p = (unit >> 3) & 511, b = unit >> 12;
    long base0 = ((long)(b * STOT) * NVOX + p) * E_ + h * 32 + lane;
    float (*q)[33] = sm[w][0]; float (*k)[33] = sm[w][1]; float (*v)[33] = sm[w][2];
#pragma unroll
    for (int s = 0; s < STOT; s++) {
        long idx = base0 + (long)s * NVOX * E_;
        q[s][lane] = Q[idx]; k[s][lane] = K[idx]; v[s][lane] = V[idx];
    }
    __syncwarp();
    for (int pid = lane; pid < STOT * STOT; pid += 32) {
        int s = pid / STOT, t = pid % STOT;
        float d = 0.f;
#pragma unroll
        for (int dd = 0; dd < 32; dd++) d += q[s][dd] * k[t][dd];
        sat[w][s][t] = d * 0.17677669529663689f;
    }
    __syncwarp();
    for (int s = 0; s < STOT; s++) {
        float x = (lane < STOT) ? sat[w][s][lane] : -1e30f;
        float m = x;
#pragma unroll
        for (int o2 = 16; o2; o2 >>= 1) m = fmaxf(m, __shfl_xor_sync(0xffffffffu, m, o2));
        float e = (lane < STOT) ? expf(x - m) : 0.f;
        float su = e;
#pragma unroll
        for (int o2 = 16; o2; o2 >>= 1) su += __shfl_xor_sync(0xffffffffu, su, o2);
        if (lane < STOT) sat[w][s][lane] = e / su;
    }
    __syncwarp();
    for (int s = 0; s < STOT; s++) {
        float a = 0.f;
#pragma unroll
        for (int t = 0; t < STOT; t++) a += sat[w][s][t] * v[t][lane];
        O[base0 + (long)s * NVOX * E_] = a;
    }
}

// ---------------- score / loss / argmax (adds linb here) ----------------
__global__ void score_kernel(const float* __restrict__ LG, const float* __restrict__ linb,
                             const int* __restrict__ ncode, float* __restrict__ out) {
    int w = (int)((blockIdx.x * (long)blockDim.x + threadIdx.x) >> 5);
    int lane = threadIdx.x & 31;
    if (w >= NB * PRED * NVOX) return;
    const float* row = LG + (long)w * NE_;
    float vals[16]; float bv = -1e30f; int bi = 0x7fffffff;
#pragma unroll
    for (int i = 0; i < 16; i++) {
        int c = lane + 32 * i;
        vals[i] = row[c] + linb[c];
        if (vals[i] > bv) { bv = vals[i]; bi = c; }
    }
#pragma unroll
    for (int o = 16; o; o >>= 1) {
        float ov = __shfl_xor_sync(0xffffffffu, bv, o);
        int oi = __shfl_xor_sync(0xffffffffu, bi, o);
        if (ov > bv || (ov == bv && oi < bi)) { bv = ov; bi = oi; }
    }
    float m = bv, se = 0.f;
#pragma unroll
    for (int i = 0; i < 16; i++) se += expf(vals[i] - m);
#pragma unroll
    for (int o = 16; o; o >>= 1) se += __shfl_xor_sync(0xffffffffu, se, o);
    float logZ = m + logf(se);
    int b = w >> 11, t = (w >> 9) & 3, p = w & 511;
#pragma unroll
    for (int i = 0; i < 16; i++) {
        int c = lane + 32 * i;
        out[(long)(((b * NE_ + c) * PRED + t) * NVOX + p)] = vals[i];
    }
    if (lane == 0) {
        int tgt = ncode[w];
        g_LP[w] = (row[tgt] + linb[tgt]) - logZ;
        out[SCORE_ELEMS + 1 + w] = (float)bi;
    }
}

__global__ void finish_kernel(float* __restrict__ out) {
    __shared__ float sh[256];
    float s = 0.f;
    for (int i = threadIdx.x; i < NB * PRED * NVOX; i += 256) s += g_LP[i];
    sh[threadIdx.x] = s;
    __syncthreads();
    for (int o = 128; o; o >>= 1) {
        if (threadIdx.x < o) sh[threadIdx.x] += sh[threadIdx.x + o];
        __syncthreads();
    }
    if (threadIdx.x == 0) out[SCORE_ELEMS] = -sh[0] / (float)(NB * PRED * NVOX);
}

#define GEMM_SMEM (16640 * 4)

// ---------------- driver ----------------
extern "C" void kernel_launch(void* const* d_in, const int* in_sizes, int n_in,
                              void* d_out, int out_size) {
    const int* code = (const int*)d_in[0];
    const int* ncode = (const int*)d_in[1];
    const float* emb = (const float*)d_in[2];
    const float* pos = (const float*)d_in[3];
    const float* ln1s = (const float*)d_in[4]; const float* ln1b = (const float*)d_in[5];
    const float* ln2s = (const float*)d_in[6]; const float* ln2b = (const float*)d_in[7];
    const float* wq = (const float*)d_in[8];  const float* bq = (const float*)d_in[9];
    const float* wk = (const float*)d_in[10]; const float* bk = (const float*)d_in[11];
    const float* wv = (const float*)d_in[12]; const float* bv = (const float*)d_in[13];
    const float* wo = (const float*)d_in[14]; const float* bo = (const float*)d_in[15];
    const float* w1 = (const float*)d_in[16]; const float* b1 = (const float*)d_in[17];
    const float* w2 = (const float*)d_in[18]; const float* b2 = (const float*)d_in[19];
    const float* lnfs = (const float*)d_in[20]; const float* lnfb = (const float*)d_in[21];
    const float* decw = (const float*)d_in[22]; const float* decb = (const float*)d_in[23];
    const float* declns = (const float*)d_in[24]; const float* declnb = (const float*)d_in[25];
    const float* linw = (const float*)d_in[26]; const float* linb = (const float*)d_in[27];
    float* out = (float*)d_out;

    float *X,*H,*Qb,*Kb,*Vb,*Ab,*HIDb,*XFb,*Y2b,*Y3b,*LGb,*WV,*WM,*WU;
    cudaGetSymbolAddress((void**)&X, g_X);   cudaGetSymbolAddress((void**)&H, g_H);
    cudaGetSymbolAddress((void**)&Qb, g_Q);  cudaGetSymbolAddress((void**)&Kb, g_K);
    cudaGetSymbolAddress((void**)&Vb, g_V);  cudaGetSymbolAddress((void**)&Ab, g_A);
    cudaGetSymbolAddress((void**)&HIDb, g_HID);
    cudaGetSymbolAddress((void**)&XFb, g_XF); cudaGetSymbolAddress((void**)&Y2b, g_Y2);
    cudaGetSymbolAddress((void**)&Y3b, g_Y3); cudaGetSymbolAddress((void**)&LGb, g_LG);
    cudaGetSymbolAddress((void**)&WV, g_WV);  cudaGetSymbolAddress((void**)&WM, g_WM);
    cudaGetSymbolAddress((void**)&WU, g_WU);

    cudaFuncSetAttribute(wg_gemm<256,256>, cudaFuncAttributeMaxDynamicSharedMemorySize, GEMM_SMEM);
    cudaFuncSetAttribute(wg_gemm<256,512>, cudaFuncAttributeMaxDynamicSharedMemorySize, GEMM_SMEM);
    cudaFuncSetAttribute(wg_gemm<512,256>, cudaFuncAttributeMaxDynamicSharedMemorySize, GEMM_SMEM);

    embed_kernel<<<40960, 256>>>(code, emb, pos, X);

    for (int l = 0; l < NL; l++) {
        const float* wq_l = wq + (long)l*27*256*256; const float* wk_l = wk + (long)l*27*256*256;
        const float* wv_l = wv + (long)l*27*256*256; const float* wo_l = wo + (long)l*27*256*256;
        const float* w1_l = w1 + (long)l*27*256*512; const float* w2_l = w2 + (long)l*27*512*256;

        ln_kernel<<<5120, 256>>>(X, H, ln1s + l*E_, ln1b + l*E_, NITEMS*NVOX, STOT, STOT, 0);
        wg_intrans<256><<<NITEMS*64, 256>>>(H, WV, NITEMS, NITEMS, NITEMS, 0);
        wg_wtrans<<<256, 256>>>(wq_l, WU, 256, 256);
        wg_gemm<256,256><<<dim3(64,40,2), 256, GEMM_SMEM>>>(WV, WU, WM, 5120);
        wg_outtrans<0><<<NITEMS*64, 256>>>(WM, bq + l*E_, nullptr, Qb, 256, NITEMS, NITEMS, NITEMS, 0);
        wg_wtrans<<<256, 256>>>(wk_l, WU, 256, 256);
        wg_gemm<256,256><<<dim3(64,40,2), 256, GEMM_SMEM>>>(WV, WU, WM, 5120);
        wg_outtrans<0><<<NITEMS*64, 256>>>(WM, bk + l*E_, nullptr, Kb, 256, NITEMS, NITEMS, NITEMS, 0);
        wg_wtrans<<<256, 256>>>(wv_l, WU, 256, 256);
        wg_gemm<256,256><<<dim3(64,40,2), 256, GEMM_SMEM>>>(WV, WU, WM, 5120);
        wg_outtrans<0><<<NITEMS*64, 256>>>(WM, bv + l*E_, nullptr, Vb, 256, NITEMS, NITEMS, NITEMS, 0);
        attn_kernel<<<4096, 128>>>(Qb, Kb, Vb, Ab);

        if (l < NL - 1) {
            wg_intrans<256><<<NITEMS*64, 256>>>(Ab, WV, NITEMS, NITEMS, NITEMS, 0);
            wg_wtrans<<<256, 256>>>(wo_l, WU, 256, 256);
            wg_gemm<256,256><<<dim3(64,40,2), 256, GEMM_SMEM>>>(WV, WU, WM, 5120);
            wg_outtrans<1><<<NITEMS*64, 256>>>(WM, bo + l*E_, X, X, 256, NITEMS, NITEMS, NITEMS, 0);
            ln_kernel<<<5120, 256>>>(X, H, ln2s + l*E_, ln2b + l*E_, NITEMS*NVOX, STOT, STOT, 0);
            wg_intrans<256><<<NITEMS*64, 256>>>(H, WV, NITEMS, NITEMS, NITEMS, 0);
            wg_wtrans<<<256, 256>>>(w1_l, WU, 256, 512);
            wg_gemm<256,512><<<dim3(64,40,4), 256, GEMM_SMEM>>>(WV, WU, WM, 5120);
            wg_outtrans<2><<<NITEMS*64, 256>>>(WM, b1 + l*HID_, nullptr, HIDb, 512, NITEMS, NITEMS, NITEMS, 0);
            wg_intrans<512><<<NITEMS*64, 256>>>(HIDb, WV, NITEMS, NITEMS, NITEMS, 0);
            wg_wtrans<<<512, 256>>>(w2_l, WU, 512, 256);
            wg_gemm<512,256><<<dim3(64,40,2), 256, GEMM_SMEM>>>(WV, WU, WM, 5120);
            wg_outtrans<1><<<NITEMS*64, 256>>>(WM, b2 + l*E_, X, X, 256, NITEMS, NITEMS, NITEMS, 0);
        } else {
            // last layer: only s >= BPTT feeds the output
            wg_intrans<256><<<NTAIL*64, 256>>>(Ab, WV, NTAIL, PRED, STOT, BPTT);
            wg_wtrans<<<256, 256>>>(wo_l, WU, 256, 256);
            wg_gemm<256,256><<<dim3(64,8,2), 256, GEMM_SMEM>>>(WV, WU, WM, 1024);
            wg_outtrans<1><<<NTAIL*64, 256>>>(WM, bo + l*E_, X, X, 256, NTAIL, PRED, STOT, BPTT);
            ln_kernel<<<1024, 256>>>(X, H, ln2s + l*E_, ln2b + l*E_, NTAIL*NVOX, PRED, STOT, BPTT);
            wg_intrans<256><<<NTAIL*64, 256>>>(H, WV, NTAIL, NTAIL, NTAIL, 0);
            wg_wtrans<<<256, 256>>>(w1_l, WU, 256, 512);
            wg_gemm<256,512><<<dim3(64,8,4), 256, GEMM_SMEM>>>(WV, WU, WM, 1024);
            wg_outtrans<2><<<NTAIL*64, 256>>>(WM, b1 + l*HID_, nullptr, HIDb, 512, NTAIL, NTAIL, NTAIL, 0);
            wg_intrans<512><<<NTAIL*64, 256>>>(HIDb, WV, NTAIL, NTAIL, NTAIL, 0);
            wg_wtrans<<<512, 256>>>(w2_l, WU, 512, 256);
            wg_gemm<512,256><<<dim3(64,8,2), 256, GEMM_SMEM>>>(WV, WU, WM, 1024);
            wg_outtrans<1><<<NTAIL*64, 256>>>(WM, b2 + l*E_, X, X, 256, NTAIL, PRED, STOT, BPTT);
        }
    }

    // tail
    ln_kernel<<<1024, 256>>>(X, XFb, lnfs, lnfb, NTAIL*NVOX, PRED, STOT, BPTT);
    wg_intrans<256><<<NTAIL*64, 256>>>(XFb, WV, NTAIL, NTAIL, NTAIL, 0);
    wg_wtrans<<<256, 256>>>(decw, WU, 256, 256);
    wg_gemm<256,256><<<dim3(64,8,2), 256, GEMM_SMEM>>>(WV, WU, WM, 1024);
    wg_outtrans<2><<<NTAIL*64, 256>>>(WM, decb, nullptr, Y2b, 256, NTAIL, NTAIL, NTAIL, 0);
    ln_kernel<<<1024, 256>>>(Y2b, Y3b, declns, declnb, NTAIL*NVOX, PRED, PRED, 0);
    // vocab projection: plain GEMM through the same core (p=0, U=linw [256][512])
    wg_gemm<256,512><<<dim3(1,64,4), 256, GEMM_SMEM>>>(Y3b, linw, LGb, 8192);
    score_kernel<<<1024, 256>>>(LGb, linb, ncode, out);
    finish_kernel<<<1, 256>>>(out);
}